// round 7
// baseline (speedup 1.0000x reference)
#include <cuda_runtime.h>
#include <cstdint>

#define NN_ 4096
#define FIN_ 512
#define HID_ 256
#define NE_MAX 131072
#define NH_ (NN_ * HID_)

// ---------------- scratch ----------------
__device__ float g_h[NH_];
__device__ float g_z0[3][NH_];
__device__ float g_bufA[3][NH_];
__device__ float g_t1[3][NH_];
__device__ float g_t2[3][NH_];
__device__ float g_u1[3][NH_];
__device__ float g_zr[3][NH_];
__device__ float g_sig[3][(size_t)NN_ * NN_];
__device__ float g_part[3][4 * NH_];
__device__ float g_Xr[NN_ * FIN_];
__device__ float g_Wr[FIN_ * HID_ + 6 * HID_ * HID_];

__device__ int   g_cnt[NN_];
__device__ int   g_ptrR[NN_ + 1];
__device__ int   g_nextR[NN_];
__device__ int   g_colR[NE_MAX];
__device__ float g_valR[NE_MAX];
__device__ int   g_ptrC[NN_ + 1];
__device__ int   g_nextC[NN_];
__device__ int   g_colC[NE_MAX];
__device__ float g_valC[NE_MAX];

// ---------------- helpers ----------------
__device__ __forceinline__ uint32_t smem_u32(const void* p) {
    uint32_t a;
    asm("{ .reg .u64 t; cvta.to.shared.u64 t, %1; cvt.u32.u64 %0, t; }" : "=r"(a) : "l"(p));
    return a;
}
__device__ __forceinline__ float rtf32(float x) {
    uint32_t u;
    asm("cvt.rna.tf32.f32 %0, %1;" : "=r"(u) : "f"(x));
    return __uint_as_float(u);
}
#define CP16(d, s) asm volatile("cp.async.ca.shared.global [%0], [%1], 16;" :: "r"(d), "l"(s))
#define CPCOMMIT() asm volatile("cp.async.commit_group;" ::: "memory")
#define CPWAIT0() asm volatile("cp.async.wait_group 0;" ::: "memory")

// ---------------- tf32 mma.sync GEMM (4 warps, 64x64 warp tile) ----------------
// C = epi(A[M,K] @ op(B)). TRB: B is [Nc,K] (A@B^T), else [K,Nc].
// EPI: 0 none, 2 sigmoid. SMODE: 0 plain, 1 rtf32 store. SYM: mirror via smem transpose.
// Batched: blockIdx.z = branch (strides aS/bS/cS elements); blockIdx.y = split-K (C += y*cstride).
static constexpr int SMEM_BYTES = (9216 + 2 * 4608) * 4;  // 73728

template <bool TRB, int EPI, bool SYM, int SMODE>
__global__ __launch_bounds__(128) void tcg(
    const float* __restrict__ A, const float* __restrict__ B,
    float* __restrict__ C, int Nc, int K, int KCn, int tilesN, long long cstride,
    long long aS, long long bS, long long cS) {
    extern __shared__ float sm[];
    const int tid = threadIdx.x, lane = tid & 31, wid = tid >> 5;
    const int wm = wid >> 1, wn = wid & 1;
    const int g = lane >> 2, t = lane & 3;

    A += (size_t)blockIdx.z * aS;
    B += (size_t)blockIdx.z * bS;
    C += (size_t)blockIdx.z * cS + (size_t)blockIdx.y * cstride;

    int i, j;
    if (SYM) {
        int b = blockIdx.x, row = 0;
        while (b >= tilesN - row) { b -= tilesN - row; row++; }
        i = row; j = row + b;
    } else {
        i = blockIdx.x / tilesN; j = blockIdx.x % tilesN;
    }
    const int m0 = i * 128, n0 = j * 128;
    const int kb = blockIdx.y * KCn;

    const uint32_t sbase = smem_u32(sm);
    const int BSTR = TRB ? 4608 : 4352;

    float acc[4][8][4];
    #pragma unroll
    for (int a = 0; a < 4; a++)
        #pragma unroll
        for (int b = 0; b < 8; b++)
            #pragma unroll
            for (int c = 0; c < 4; c++) acc[a][b][c] = 0.f;

    auto load_tile = [&](int akc, int buf) {
        {   // A: 128 rows x 32 cols, one row per thread
            const float* s = A + (size_t)(m0 + tid) * K + akc * 32;
            uint32_t d = sbase + (uint32_t)((buf * 4608 + tid * 36) * 4);
            #pragma unroll
            for (int q = 0; q < 8; q++) CP16(d + q * 16, s + q * 4);
        }
        if (TRB) {
            const float* s = B + (size_t)(n0 + tid) * K + akc * 32;
            uint32_t d = sbase + (uint32_t)((9216 + buf * 4608 + tid * 36) * 4);
            #pragma unroll
            for (int q = 0; q < 8; q++) CP16(d + q * 16, s + q * 4);
        } else {  // 32 rows x 128 cols
            int r = tid >> 2, c0 = (tid & 3) * 32;
            const float* s = B + (size_t)(akc * 32 + r) * Nc + n0 + c0;
            uint32_t d = sbase + (uint32_t)((9216 + buf * 4352 + r * 136 + c0) * 4);
            #pragma unroll
            for (int q = 0; q < 8; q++) CP16(d + q * 16, s + q * 4);
        }
    };

    load_tile(kb, 0);
    CPCOMMIT();
    int buf = 0;
    for (int c = 0; c < KCn; c++) {
        CPWAIT0();
        __syncthreads();
        if (c + 1 < KCn) { load_tile(kb + c + 1, buf ^ 1); CPCOMMIT(); }
        const uint32_t* As = (const uint32_t*)sm + buf * 4608;
        const uint32_t* Bs = (const uint32_t*)sm + 9216 + buf * BSTR;
        #pragma unroll
        for (int ks = 0; ks < 4; ks++) {
            const int k0 = ks * 8;
            uint32_t a[4][4];
            #pragma unroll
            for (int mf = 0; mf < 4; mf++) {
                const uint32_t* ap = As + (wm * 64 + mf * 16 + g) * 36 + k0 + t;
                a[mf][0] = ap[0];
                a[mf][1] = ap[8 * 36];
                a[mf][2] = ap[4];
                a[mf][3] = ap[8 * 36 + 4];
            }
            #pragma unroll
            for (int nf = 0; nf < 8; nf++) {
                uint32_t b0, b1;
                if (TRB) {
                    const uint32_t* bp = Bs + (wn * 64 + nf * 8 + g) * 36 + k0 + t;
                    b0 = bp[0]; b1 = bp[4];
                } else {
                    const uint32_t* bp = Bs + (k0 + t) * 136 + wn * 64 + nf * 8 + g;
                    b0 = bp[0]; b1 = bp[544];
                }
                #pragma unroll
                for (int mf = 0; mf < 4; mf++) {
                    asm volatile(
                        "mma.sync.aligned.m16n8k8.row.col.f32.tf32.tf32.f32 "
                        "{%0,%1,%2,%3}, {%4,%5,%6,%7}, {%8,%9}, {%0,%1,%2,%3};"
                        : "+f"(acc[mf][nf][0]), "+f"(acc[mf][nf][1]),
                          "+f"(acc[mf][nf][2]), "+f"(acc[mf][nf][3])
                        : "r"(a[mf][0]), "r"(a[mf][1]), "r"(a[mf][2]), "r"(a[mf][3]),
                          "r"(b0), "r"(b1));
                }
            }
        }
        __syncthreads();
        buf ^= 1;
    }

    // epilogue (row-major coalesced; SYM stages tile in smem for coalesced mirror)
    #pragma unroll
    for (int mf = 0; mf < 4; mf++) {
        int lr = wm * 64 + mf * 16 + g;
        #pragma unroll
        for (int nf = 0; nf < 8; nf++) {
            int lc = wn * 64 + nf * 8 + 2 * t;
            float w[4];
            #pragma unroll
            for (int q = 0; q < 4; q++) {
                float x = acc[mf][nf][q];
                if (EPI == 2) x = 1.f / (1.f + __expf(-x));
                w[q] = (SMODE == 1) ? rtf32(x) : x;
            }
            *reinterpret_cast<float2*>(&C[(size_t)(m0 + lr) * Nc + n0 + lc]) = make_float2(w[0], w[1]);
            *reinterpret_cast<float2*>(&C[(size_t)(m0 + lr + 8) * Nc + n0 + lc]) = make_float2(w[2], w[3]);
            if (SYM) {
                sm[lr * 129 + lc] = w[0];
                sm[lr * 129 + lc + 1] = w[1];
                sm[(lr + 8) * 129 + lc] = w[2];
                sm[(lr + 8) * 129 + lc + 1] = w[3];
            }
        }
    }
    if (SYM && i != j) {
        __syncthreads();
        #pragma unroll 4
        for (int c = 0; c < 128; c++)
            C[(size_t)(n0 + c) * Nc + m0 + tid] = sm[tid * 129 + c];
    }
}

// ---------------- split-K reduce (batched over blockIdx.y = branch) ----------------
__global__ void reduce4_round(const float* __restrict__ p, float* __restrict__ o,
                              long long pS, long long oS) {
    const float* pp = p + (size_t)blockIdx.y * pS;
    float* oo = o + (size_t)blockIdx.y * oS;
    int i = (blockIdx.x * blockDim.x + threadIdx.x) * 4;
    float4 a = *reinterpret_cast<const float4*>(pp + i);
    float4 b = *reinterpret_cast<const float4*>(pp + NH_ + i);
    float4 c = *reinterpret_cast<const float4*>(pp + 2 * NH_ + i);
    float4 d = *reinterpret_cast<const float4*>(pp + 3 * NH_ + i);
    float4 r;
    r.x = rtf32(a.x + b.x + c.x + d.x);
    r.y = rtf32(a.y + b.y + c.y + d.y);
    r.z = rtf32(a.z + b.z + c.z + d.z);
    r.w = rtf32(a.w + b.w + c.w + d.w);
    *reinterpret_cast<float4*>(oo + i) = r;
}
__global__ void reduce4_addrelu(const float* __restrict__ p, const float* __restrict__ u,
                                float* __restrict__ z, float* __restrict__ zr,
                                long long pS, long long uS, long long zS, long long zrS) {
    const float* pp = p + (size_t)blockIdx.y * pS;
    const float* uu4 = u + (size_t)blockIdx.y * uS;
    float* zz4 = z + (size_t)blockIdx.y * zS;
    float* rr4 = zr + (size_t)blockIdx.y * zrS;
    int i = (blockIdx.x * blockDim.x + threadIdx.x) * 4;
    float4 a = *reinterpret_cast<const float4*>(pp + i);
    float4 b = *reinterpret_cast<const float4*>(pp + NH_ + i);
    float4 c = *reinterpret_cast<const float4*>(pp + 2 * NH_ + i);
    float4 d = *reinterpret_cast<const float4*>(pp + 3 * NH_ + i);
    float4 uu = *reinterpret_cast<const float4*>(uu4 + i);
    float4 zz, rr;
    zz.x = fmaxf(a.x + b.x + c.x + d.x + uu.x, 0.f);
    zz.y = fmaxf(a.y + b.y + c.y + d.y + uu.y, 0.f);
    zz.z = fmaxf(a.z + b.z + c.z + d.z + uu.z, 0.f);
    zz.w = fmaxf(a.w + b.w + c.w + d.w + uu.w, 0.f);
    rr.x = rtf32(zz.x); rr.y = rtf32(zz.y); rr.z = rtf32(zz.z); rr.w = rtf32(zz.w);
    *reinterpret_cast<float4*>(zz4 + i) = zz;
    *reinterpret_cast<float4*>(rr4 + i) = rr;
}

// ---------------- CSR build ----------------
__global__ void zero_int_kernel(int* p, int n) {
    int i = blockIdx.x * blockDim.x + threadIdx.x;
    if (i < n) p[i] = 0;
}
__global__ void hist_kernel(const int* __restrict__ k, int* __restrict__ c, int ne) {
    int i = blockIdx.x * blockDim.x + threadIdx.x;
    if (i < ne) atomicAdd(&c[k[i]], 1);
}
__global__ void exscan_kernel(const int* __restrict__ cnt, int* __restrict__ rp, int* __restrict__ nx) {
    __shared__ int sums[1024];
    int t = threadIdx.x;
    int v0 = cnt[t * 4], v1 = cnt[t * 4 + 1], v2 = cnt[t * 4 + 2], v3 = cnt[t * 4 + 3];
    sums[t] = v0 + v1 + v2 + v3;
    __syncthreads();
    for (int off = 1; off < 1024; off <<= 1) {
        int x = (t >= off) ? sums[t - off] : 0;
        __syncthreads();
        sums[t] += x;
        __syncthreads();
    }
    int run = (t > 0) ? sums[t - 1] : 0;
    rp[t * 4] = run; nx[t * 4] = run; run += v0;
    rp[t * 4 + 1] = run; nx[t * 4 + 1] = run; run += v1;
    rp[t * 4 + 2] = run; nx[t * 4 + 2] = run; run += v2;
    rp[t * 4 + 3] = run; nx[t * 4 + 3] = run; run += v3;
    if (t == 1023) rp[4096] = run;
}
__global__ void scatter_kernel(const int* __restrict__ k, const int* __restrict__ o,
                               const float* __restrict__ v, int* __restrict__ nx,
                               int* __restrict__ ec, float* __restrict__ ev, int ne) {
    int i = blockIdx.x * blockDim.x + threadIdx.x;
    if (i < ne) {
        int p = atomicAdd(&nx[k[i]], 1);
        ec[p] = o[i];
        ev[p] = v[i];
    }
}

// ---------------- SpMM (batched over blockIdx.y = branch) ----------------
__global__ __launch_bounds__(HID_) void spmm_csr_kernel(
    const int* __restrict__ rowptr, const int* __restrict__ ecol,
    const float* __restrict__ eval, const float* __restrict__ in,
    float* __restrict__ out, int mode, long long inS, long long outS) {
    const float* inp = in + (size_t)blockIdx.y * inS;
    float* outp = out + (size_t)blockIdx.y * outS;
    int r = blockIdx.x, f = threadIdx.x;
    int s = rowptr[r], e = rowptr[r + 1];
    __shared__ int   scol[HID_];
    __shared__ float sval[HID_];
    float acc = 0.f;
    for (int base = s; base < e; base += HID_) {
        int n = e - base;
        if (n > HID_) n = HID_;
        if (f < n) { scol[f] = ecol[base + f]; sval[f] = eval[base + f]; }
        __syncthreads();
        #pragma unroll 4
        for (int i = 0; i < n; i++) acc += sval[i] * inp[scol[i] * HID_ + f];
        __syncthreads();
    }
    if (mode >= 1) acc = fmaxf(acc, 0.f);
    if (mode == 2) acc = rtf32(acc);
    outp[r * HID_ + f] = acc;
}

// ---------------- prep / head ----------------
__global__ void round_copy_kernel(const float* __restrict__ x, float* __restrict__ y, int n) {
    int i = blockIdx.x * blockDim.x + threadIdx.x;
    if (i < n) y[i] = rtf32(x[i]);
}
__global__ void pred_kernel(const float* __restrict__ z_iv, const float* __restrict__ z_c,
                            const float* __restrict__ linW, const float* __restrict__ linb,
                            float* __restrict__ out) {
    int i = blockIdx.x * blockDim.x + threadIdx.x;
    if (i >= NN_) return;
    float l0 = linb[0], l1 = linb[1];
    #pragma unroll 4
    for (int k = 0; k < HID_; k++) {
        float v = z_iv[i * HID_ + k];
        l0 += v * linW[k * 2];
        l1 += v * linW[k * 2 + 1];
    }
    #pragma unroll 4
    for (int k = 0; k < HID_; k++) {
        float v = z_c[i * HID_ + k];
        l0 += v * linW[(HID_ + k) * 2];
        l1 += v * linW[(HID_ + k) * 2 + 1];
    }
    float m = fmaxf(l0, l1);
    float lse = m + logf(expf(l0 - m) + expf(l1 - m));
    out[i * 2] = l0 - lse;
    out[i * 2 + 1] = l1 - lse;
}
__global__ void write_loss_kernel(float* p) { *p = 0.f; }

// ---------------- host ----------------
static void* sym(const void* s) { void* p = nullptr; cudaGetSymbolAddress(&p, s); return p; }

extern "C" void kernel_launch(void* const* d_in, const int* in_sizes, int n_in,
                              void* d_out, int out_size) {
    const float* X     = (const float*)d_in[0];
    const int*   arows = (const int*)d_in[1];
    const int*   acols = (const int*)d_in[2];
    const float* avals = (const float*)d_in[3];
    const float* Wsh   = (const float*)d_in[4];
    const float* Wb[3] = {(const float*)d_in[5], (const float*)d_in[6], (const float*)d_in[7]};
    const float* Wg[3] = {(const float*)d_in[8], (const float*)d_in[9], (const float*)d_in[10]};
    const float* linW  = (const float*)d_in[11];
    const float* linb  = (const float*)d_in[12];
    float* out = (float*)d_out;
    int ne = in_sizes[1];

    float* h    = (float*)sym(g_h);
    float* Xr   = (float*)sym(g_Xr);
    float* Wr   = (float*)sym(g_Wr);
    float* z0   = (float*)sym(g_z0);
    float* bufA = (float*)sym(g_bufA);
    float* t1   = (float*)sym(g_t1);
    float* t2   = (float*)sym(g_t2);
    float* u1   = (float*)sym(g_u1);
    float* zr   = (float*)sym(g_zr);
    float* sig  = (float*)sym(g_sig);
    float* part = (float*)sym(g_part);
    int* cnt = (int*)sym(g_cnt);
    int* ptrR = (int*)sym(g_ptrR); int* nextR = (int*)sym(g_nextR);
    int* colR = (int*)sym(g_colR); float* valR = (float*)sym(g_valR);
    int* ptrC = (int*)sym(g_ptrC); int* nextC = (int*)sym(g_nextC);
    int* colC = (int*)sym(g_colC); float* valC = (float*)sym(g_valC);

    cudaFuncSetAttribute(tcg<false, 0, false, 0>, cudaFuncAttributeMaxDynamicSharedMemorySize, SMEM_BYTES);
    cudaFuncSetAttribute(tcg<false, 0, false, 1>, cudaFuncAttributeMaxDynamicSharedMemorySize, SMEM_BYTES);
    cudaFuncSetAttribute(tcg<true, 2, true, 1>, cudaFuncAttributeMaxDynamicSharedMemorySize, SMEM_BYTES);
    cudaFuncSetAttribute(tcg<true, 0, true, 0>, cudaFuncAttributeMaxDynamicSharedMemorySize, SMEM_BYTES);

    const long long SNN = (long long)NN_ * NN_;   // sig branch stride
    const long long SZ4 = 4LL * NH_;              // part branch stride
    const long long SZO = 17825792LL;             // output z/rec branch stride
    const size_t lossoff = 53477376ul, predoff = 53477377ul;
    const size_t roff0 = 1048576ul;

    int neb = (ne + 255) / 256;

    // prologue (launch #6 = h GEMM for ncu -s 5 -c 1)
    round_copy_kernel<<<(NN_ * FIN_ + 255) / 256, 256>>>(X, Xr, NN_ * FIN_);
    round_copy_kernel<<<(FIN_ * HID_ + 255) / 256, 256>>>(Wsh, Wr, FIN_ * HID_);
    zero_int_kernel<<<16, 256>>>(cnt, NN_);
    hist_kernel<<<neb, 256>>>(arows, cnt, ne);
    exscan_kernel<<<1, 1024>>>(cnt, ptrR, nextR);
    tcg<false, 0, false, 0><<<64, 128, SMEM_BYTES>>>(Xr, Wr, bufA, 256, 512, 16, 2, 0, 0, 0, 0);
    scatter_kernel<<<neb, 256>>>(arows, acols, avals, nextR, colR, valR, ne);
    zero_int_kernel<<<16, 256>>>(cnt, NN_);
    hist_kernel<<<neb, 256>>>(acols, cnt, ne);
    exscan_kernel<<<1, 1024>>>(cnt, ptrC, nextC);
    scatter_kernel<<<neb, 256>>>(acols, arows, avals, nextC, colC, valC, ne);
    for (int b = 0; b < 3; b++) {
        round_copy_kernel<<<256, 256>>>(Wb[b], Wr + FIN_ * HID_ + b * 65536, HID_ * HID_);
        round_copy_kernel<<<256, 256>>>(Wg[b], Wr + FIN_ * HID_ + (3 + b) * 65536, HID_ * HID_);
    }
    // h = rtf32(relu(spmm(Xr @ Wsh)))
    spmm_csr_kernel<<<NN_, HID_>>>(ptrR, colR, valR, bufA, h, 2, 0, 0);

    // ---- all three branches batched via blockIdx.z ----
    const float* Wb0 = Wr + FIN_ * HID_;
    const float* Wg0 = Wr + FIN_ * HID_ + 3 * 65536;

    // z0 = rtf32(relu(spmm(h @ Wb)))
    tcg<false, 0, false, 0><<<dim3(64, 1, 3), 128, SMEM_BYTES>>>(
        h, Wb0, bufA, 256, 256, 8, 2, 0, 0, 65536, NH_);
    spmm_csr_kernel<<<dim3(NN_, 3), HID_>>>(ptrR, colR, valR, bufA, z0, 2, NH_, NH_);
    // sig = rtf32(sigmoid(z0 @ z0^T))  [symmetric]
    tcg<true, 2, true, 1><<<dim3(528, 1, 3), 128, SMEM_BYTES>>>(
        z0, z0, sig, 4096, 256, 8, 32, 0, NH_, NH_, SNN);
    // hW = rtf32(z0 @ Wg)
    tcg<false, 0, false, 1><<<dim3(64, 1, 3), 128, SMEM_BYTES>>>(
        z0, Wg0, bufA, 256, 256, 8, 2, 0, NH_, 65536, NH_);
    // t1 = A^T @ hW
    spmm_csr_kernel<<<dim3(NN_, 3), HID_>>>(ptrC, colC, valC, bufA, t1, 0, NH_, NH_);
    // t2 = rtf32(sig @ hW)  [split-K x4]
    tcg<false, 0, false, 0><<<dim3(64, 4, 3), 128, SMEM_BYTES>>>(
        sig, bufA, part, 256, 4096, 32, 2, NH_, SNN, NH_, SZ4);
    reduce4_round<<<dim3(1024, 3), 256>>>(part, t2, SZ4, NH_);
    // u1 = A @ t1
    spmm_csr_kernel<<<dim3(NN_, 3), HID_>>>(ptrR, colR, valR, t1, u1, 0, NH_, NH_);
    // z = relu(sig @ t2 + u1)  [split-K x4]
    tcg<false, 0, false, 0><<<dim3(64, 4, 3), 128, SMEM_BYTES>>>(
        sig, t2, part, 256, 4096, 32, 2, NH_, SNN, NH_, SZ4);
    reduce4_addrelu<<<dim3(1024, 3), 256>>>(part, u1, out, zr, SZ4, NH_, SZO, NH_);
    // rec = zr @ zr^T  [symmetric]
    tcg<true, 0, true, 0><<<dim3(528, 1, 3), 128, SMEM_BYTES>>>(
        zr, zr, out + roff0, 4096, 256, 8, 32, 0, NH_, NH_, SZO);

    pred_kernel<<<16, 256>>>(out, out + SZO, linW, linb, out + predoff);
    write_loss_kernel<<<1, 1>>>(out + lossoff);
}

// round 8
// speedup vs baseline: 1.1933x; 1.1933x over previous
#include <cuda_runtime.h>
#include <cstdint>

#define NN_ 4096
#define FIN_ 512
#define HID_ 256
#define NE_MAX 131072
#define NH_ (NN_ * HID_)

// ---------------- scratch ----------------
__device__ float g_h[NH_];
__device__ float g_z0[3][NH_];
__device__ float g_bufA[3][NH_];
__device__ float g_t1[3][NH_];
__device__ float g_t2[3][NH_];
__device__ float g_u1[3][NH_];
__device__ float g_zr[3][NH_];
__device__ float g_sig[3][(size_t)NN_ * NN_];
__device__ float g_part[3][4 * NH_];
__device__ float g_Xr[NN_ * FIN_];
__device__ float g_Wr[FIN_ * HID_ + 6 * HID_ * HID_];

__device__ int   g_cnt[NN_];
__device__ int   g_ptrR[NN_ + 1];
__device__ int   g_nextR[NN_];
__device__ int   g_colR[NE_MAX];
__device__ float g_valR[NE_MAX];
__device__ int   g_ptrC[NN_ + 1];
__device__ int   g_nextC[NN_];
__device__ int   g_colC[NE_MAX];
__device__ float g_valC[NE_MAX];

// ---------------- helpers ----------------
__device__ __forceinline__ uint32_t smem_u32(const void* p) {
    uint32_t a;
    asm("{ .reg .u64 t; cvta.to.shared.u64 t, %1; cvt.u32.u64 %0, t; }" : "=r"(a) : "l"(p));
    return a;
}
__device__ __forceinline__ float rtf32(float x) {
    uint32_t u;
    asm("cvt.rna.tf32.f32 %0, %1;" : "=r"(u) : "f"(x));
    return __uint_as_float(u);
}
#define CP16(d, s) asm volatile("cp.async.ca.shared.global [%0], [%1], 16;" :: "r"(d), "l"(s))
#define CPCOMMIT() asm volatile("cp.async.commit_group;" ::: "memory")
#define CPWAIT0() asm volatile("cp.async.wait_group 0;" ::: "memory")

// ---------------- tf32 mma.sync GEMM (8 warps, 64x32 warp tile — R4 config) ----------------
// C = epi(A[M,K] @ op(B)). TRB: B is [Nc,K] (A@B^T), else [K,Nc].
// EPI: 0 none, 2 sigmoid. SMODE: 0 plain, 1 rtf32 store. SYM: mirror via smem transpose.
// Batched: blockIdx.z = branch (strides aS/bS/cS); blockIdx.y = split-K chunk (C += y*cstride).
static constexpr int SMEM_BYTES = (9216 + 2 * 4608) * 4;  // 73728

template <bool TRB, int EPI, bool SYM, int SMODE>
__global__ __launch_bounds__(256) void tcg(
    const float* __restrict__ A, const float* __restrict__ B,
    float* __restrict__ C, int Nc, int K, int KCn, int tilesN, long long cstride,
    long long aS, long long bS, long long cS) {
    extern __shared__ float sm[];
    const int tid = threadIdx.x, lane = tid & 31, wid = tid >> 5;
    const int wm = wid >> 2, wn = wid & 3;
    const int g = lane >> 2, t = lane & 3;

    A += (size_t)blockIdx.z * aS;
    B += (size_t)blockIdx.z * bS;
    C += (size_t)blockIdx.z * cS + (size_t)blockIdx.y * cstride;

    int i, j;
    if (SYM) {
        int b = blockIdx.x, row = 0;
        while (b >= tilesN - row) { b -= tilesN - row; row++; }
        i = row; j = row + b;
    } else {
        i = blockIdx.x / tilesN; j = blockIdx.x % tilesN;
    }
    const int m0 = i * 128, n0 = j * 128;
    const int kb = blockIdx.y * KCn;

    const uint32_t sbase = smem_u32(sm);
    const int BSTR = TRB ? 4608 : 4352;

    float acc[4][4][4];
    #pragma unroll
    for (int a = 0; a < 4; a++)
        #pragma unroll
        for (int b = 0; b < 4; b++)
            #pragma unroll
            for (int c = 0; c < 4; c++) acc[a][b][c] = 0.f;

    auto load_tile = [&](int akc, int buf) {
        {
            int r = tid >> 1, c0 = (tid & 1) * 16;
            const float* s = A + (size_t)(m0 + r) * K + akc * 32 + c0;
            uint32_t d = sbase + (uint32_t)((buf * 4608 + r * 36 + c0) * 4);
            #pragma unroll
            for (int q = 0; q < 4; q++) CP16(d + q * 16, s + q * 4);
        }
        if (TRB) {
            int r = tid >> 1, c0 = (tid & 1) * 16;
            const float* s = B + (size_t)(n0 + r) * K + akc * 32 + c0;
            uint32_t d = sbase + (uint32_t)((9216 + buf * 4608 + r * 36 + c0) * 4);
            #pragma unroll
            for (int q = 0; q < 4; q++) CP16(d + q * 16, s + q * 4);
        } else {
            int r = tid >> 3, c0 = (tid & 7) * 16;
            const float* s = B + (size_t)(akc * 32 + r) * Nc + n0 + c0;
            uint32_t d = sbase + (uint32_t)((9216 + buf * 4352 + r * 136 + c0) * 4);
            #pragma unroll
            for (int q = 0; q < 4; q++) CP16(d + q * 16, s + q * 4);
        }
    };

    load_tile(kb, 0);
    CPCOMMIT();
    int buf = 0;
    for (int c = 0; c < KCn; c++) {
        CPWAIT0();
        __syncthreads();
        if (c + 1 < KCn) { load_tile(kb + c + 1, buf ^ 1); CPCOMMIT(); }
        const uint32_t* As = (const uint32_t*)sm + buf * 4608;
        const uint32_t* Bs = (const uint32_t*)sm + 9216 + buf * BSTR;
        #pragma unroll
        for (int ks = 0; ks < 4; ks++) {
            const int k0 = ks * 8;
            uint32_t a[4][4];
            #pragma unroll
            for (int mf = 0; mf < 4; mf++) {
                const uint32_t* ap = As + (wm * 64 + mf * 16 + g) * 36 + k0 + t;
                a[mf][0] = ap[0];
                a[mf][1] = ap[8 * 36];
                a[mf][2] = ap[4];
                a[mf][3] = ap[8 * 36 + 4];
            }
            #pragma unroll
            for (int nf = 0; nf < 4; nf++) {
                uint32_t b0, b1;
                if (TRB) {
                    const uint32_t* bp = Bs + (wn * 32 + nf * 8 + g) * 36 + k0 + t;
                    b0 = bp[0]; b1 = bp[4];
                } else {
                    const uint32_t* bp = Bs + (k0 + t) * 136 + wn * 32 + nf * 8 + g;
                    b0 = bp[0]; b1 = bp[544];
                }
                #pragma unroll
                for (int mf = 0; mf < 4; mf++) {
                    asm volatile(
                        "mma.sync.aligned.m16n8k8.row.col.f32.tf32.tf32.f32 "
                        "{%0,%1,%2,%3}, {%4,%5,%6,%7}, {%8,%9}, {%0,%1,%2,%3};"
                        : "+f"(acc[mf][nf][0]), "+f"(acc[mf][nf][1]),
                          "+f"(acc[mf][nf][2]), "+f"(acc[mf][nf][3])
                        : "r"(a[mf][0]), "r"(a[mf][1]), "r"(a[mf][2]), "r"(a[mf][3]),
                          "r"(b0), "r"(b1));
                }
            }
        }
        __syncthreads();
        buf ^= 1;
    }

    // epilogue (row-major coalesced; SYM stages tile in smem for coalesced mirror)
    #pragma unroll
    for (int mf = 0; mf < 4; mf++) {
        int lr = wm * 64 + mf * 16 + g;
        #pragma unroll
        for (int nf = 0; nf < 4; nf++) {
            int lc = wn * 32 + nf * 8 + 2 * t;
            float w[4];
            #pragma unroll
            for (int q = 0; q < 4; q++) {
                float x = acc[mf][nf][q];
                if (EPI == 2) x = 1.f / (1.f + __expf(-x));
                w[q] = (SMODE == 1) ? rtf32(x) : x;
            }
            *reinterpret_cast<float2*>(&C[(size_t)(m0 + lr) * Nc + n0 + lc]) = make_float2(w[0], w[1]);
            *reinterpret_cast<float2*>(&C[(size_t)(m0 + lr + 8) * Nc + n0 + lc]) = make_float2(w[2], w[3]);
            if (SYM) {
                sm[lr * 129 + lc] = w[0];
                sm[lr * 129 + lc + 1] = w[1];
                sm[(lr + 8) * 129 + lc] = w[2];
                sm[(lr + 8) * 129 + lc + 1] = w[3];
            }
        }
    }
    if (SYM && i != j) {
        __syncthreads();
        int col = tid & 127;
        #pragma unroll 4
        for (int c = tid >> 7; c < 128; c += 2)
            C[(size_t)(n0 + c) * Nc + m0 + col] = sm[col * 129 + c];
    }
}

// ---------------- split-K reduce (batched over blockIdx.y = branch) ----------------
__global__ void reduce4_round(const float* __restrict__ p, float* __restrict__ o,
                              long long pS, long long oS) {
    const float* pp = p + (size_t)blockIdx.y * pS;
    float* oo = o + (size_t)blockIdx.y * oS;
    int i = (blockIdx.x * blockDim.x + threadIdx.x) * 4;
    float4 a = *reinterpret_cast<const float4*>(pp + i);
    float4 b = *reinterpret_cast<const float4*>(pp + NH_ + i);
    float4 c = *reinterpret_cast<const float4*>(pp + 2 * NH_ + i);
    float4 d = *reinterpret_cast<const float4*>(pp + 3 * NH_ + i);
    float4 r;
    r.x = rtf32(a.x + b.x + c.x + d.x);
    r.y = rtf32(a.y + b.y + c.y + d.y);
    r.z = rtf32(a.z + b.z + c.z + d.z);
    r.w = rtf32(a.w + b.w + c.w + d.w);
    *reinterpret_cast<float4*>(oo + i) = r;
}
__global__ void reduce4_addrelu(const float* __restrict__ p, const float* __restrict__ u,
                                float* __restrict__ z, float* __restrict__ zr,
                                long long pS, long long uS, long long zS, long long zrS) {
    const float* pp = p + (size_t)blockIdx.y * pS;
    const float* uu4 = u + (size_t)blockIdx.y * uS;
    float* zz4 = z + (size_t)blockIdx.y * zS;
    float* rr4 = zr + (size_t)blockIdx.y * zrS;
    int i = (blockIdx.x * blockDim.x + threadIdx.x) * 4;
    float4 a = *reinterpret_cast<const float4*>(pp + i);
    float4 b = *reinterpret_cast<const float4*>(pp + NH_ + i);
    float4 c = *reinterpret_cast<const float4*>(pp + 2 * NH_ + i);
    float4 d = *reinterpret_cast<const float4*>(pp + 3 * NH_ + i);
    float4 uu = *reinterpret_cast<const float4*>(uu4 + i);
    float4 zz, rr;
    zz.x = fmaxf(a.x + b.x + c.x + d.x + uu.x, 0.f);
    zz.y = fmaxf(a.y + b.y + c.y + d.y + uu.y, 0.f);
    zz.z = fmaxf(a.z + b.z + c.z + d.z + uu.z, 0.f);
    zz.w = fmaxf(a.w + b.w + c.w + d.w + uu.w, 0.f);
    rr.x = rtf32(zz.x); rr.y = rtf32(zz.y); rr.z = rtf32(zz.z); rr.w = rtf32(zz.w);
    *reinterpret_cast<float4*>(zz4 + i) = zz;
    *reinterpret_cast<float4*>(rr4 + i) = rr;
}

// ---------------- CSR build ----------------
__global__ void zero_int_kernel(int* p, int n) {
    int i = blockIdx.x * blockDim.x + threadIdx.x;
    if (i < n) p[i] = 0;
}
__global__ void hist_kernel(const int* __restrict__ k, int* __restrict__ c, int ne) {
    int i = blockIdx.x * blockDim.x + threadIdx.x;
    if (i < ne) atomicAdd(&c[k[i]], 1);
}
__global__ void exscan_kernel(const int* __restrict__ cnt, int* __restrict__ rp, int* __restrict__ nx) {
    __shared__ int sums[1024];
    int t = threadIdx.x;
    int v0 = cnt[t * 4], v1 = cnt[t * 4 + 1], v2 = cnt[t * 4 + 2], v3 = cnt[t * 4 + 3];
    sums[t] = v0 + v1 + v2 + v3;
    __syncthreads();
    for (int off = 1; off < 1024; off <<= 1) {
        int x = (t >= off) ? sums[t - off] : 0;
        __syncthreads();
        sums[t] += x;
        __syncthreads();
    }
    int run = (t > 0) ? sums[t - 1] : 0;
    rp[t * 4] = run; nx[t * 4] = run; run += v0;
    rp[t * 4 + 1] = run; nx[t * 4 + 1] = run; run += v1;
    rp[t * 4 + 2] = run; nx[t * 4 + 2] = run; run += v2;
    rp[t * 4 + 3] = run; nx[t * 4 + 3] = run; run += v3;
    if (t == 1023) rp[4096] = run;
}
__global__ void scatter_kernel(const int* __restrict__ k, const int* __restrict__ o,
                               const float* __restrict__ v, int* __restrict__ nx,
                               int* __restrict__ ec, float* __restrict__ ev, int ne) {
    int i = blockIdx.x * blockDim.x + threadIdx.x;
    if (i < ne) {
        int p = atomicAdd(&nx[k[i]], 1);
        ec[p] = o[i];
        ev[p] = v[i];
    }
}

// ---------------- SpMM (batched over blockIdx.y = branch) ----------------
__global__ __launch_bounds__(HID_) void spmm_csr_kernel(
    const int* __restrict__ rowptr, const int* __restrict__ ecol,
    const float* __restrict__ eval, const float* __restrict__ in,
    float* __restrict__ out, int mode, long long inS, long long outS) {
    const float* inp = in + (size_t)blockIdx.y * inS;
    float* outp = out + (size_t)blockIdx.y * outS;
    int r = blockIdx.x, f = threadIdx.x;
    int s = rowptr[r], e = rowptr[r + 1];
    __shared__ int   scol[HID_];
    __shared__ float sval[HID_];
    float acc = 0.f;
    for (int base = s; base < e; base += HID_) {
        int n = e - base;
        if (n > HID_) n = HID_;
        if (f < n) { scol[f] = ecol[base + f]; sval[f] = eval[base + f]; }
        __syncthreads();
        #pragma unroll 4
        for (int i = 0; i < n; i++) acc += sval[i] * inp[scol[i] * HID_ + f];
        __syncthreads();
    }
    if (mode >= 1) acc = fmaxf(acc, 0.f);
    if (mode == 2) acc = rtf32(acc);
    outp[r * HID_ + f] = acc;
}

// ---------------- prep / head ----------------
__global__ void round_copy_kernel(const float* __restrict__ x, float* __restrict__ y, int n) {
    int i = blockIdx.x * blockDim.x + threadIdx.x;
    if (i < n) y[i] = rtf32(x[i]);
}
__global__ void pred_kernel(const float* __restrict__ z_iv, const float* __restrict__ z_c,
                            const float* __restrict__ linW, const float* __restrict__ linb,
                            float* __restrict__ out) {
    int i = blockIdx.x * blockDim.x + threadIdx.x;
    if (i >= NN_) return;
    float l0 = linb[0], l1 = linb[1];
    #pragma unroll 4
    for (int k = 0; k < HID_; k++) {
        float v = z_iv[i * HID_ + k];
        l0 += v * linW[k * 2];
        l1 += v * linW[k * 2 + 1];
    }
    #pragma unroll 4
    for (int k = 0; k < HID_; k++) {
        float v = z_c[i * HID_ + k];
        l0 += v * linW[(HID_ + k) * 2];
        l1 += v * linW[(HID_ + k) * 2 + 1];
    }
    float m = fmaxf(l0, l1);
    float lse = m + logf(expf(l0 - m) + expf(l1 - m));
    out[i * 2] = l0 - lse;
    out[i * 2 + 1] = l1 - lse;
}
__global__ void write_loss_kernel(float* p) { *p = 0.f; }

// ---------------- host ----------------
static void* sym(const void* s) { void* p = nullptr; cudaGetSymbolAddress(&p, s); return p; }

extern "C" void kernel_launch(void* const* d_in, const int* in_sizes, int n_in,
                              void* d_out, int out_size) {
    const float* X     = (const float*)d_in[0];
    const int*   arows = (const int*)d_in[1];
    const int*   acols = (const int*)d_in[2];
    const float* avals = (const float*)d_in[3];
    const float* Wsh   = (const float*)d_in[4];
    const float* Wb[3] = {(const float*)d_in[5], (const float*)d_in[6], (const float*)d_in[7]};
    const float* Wg[3] = {(const float*)d_in[8], (const float*)d_in[9], (const float*)d_in[10]};
    const float* linW  = (const float*)d_in[11];
    const float* linb  = (const float*)d_in[12];
    float* out = (float*)d_out;
    int ne = in_sizes[1];

    float* h    = (float*)sym(g_h);
    float* Xr   = (float*)sym(g_Xr);
    float* Wr   = (float*)sym(g_Wr);
    float* z0   = (float*)sym(g_z0);
    float* bufA = (float*)sym(g_bufA);
    float* t1   = (float*)sym(g_t1);
    float* t2   = (float*)sym(g_t2);
    float* u1   = (float*)sym(g_u1);
    float* zr   = (float*)sym(g_zr);
    float* sig  = (float*)sym(g_sig);
    float* part = (float*)sym(g_part);
    int* cnt = (int*)sym(g_cnt);
    int* ptrR = (int*)sym(g_ptrR); int* nextR = (int*)sym(g_nextR);
    int* colR = (int*)sym(g_colR); float* valR = (float*)sym(g_valR);
    int* ptrC = (int*)sym(g_ptrC); int* nextC = (int*)sym(g_nextC);
    int* colC = (int*)sym(g_colC); float* valC = (float*)sym(g_valC);

    cudaFuncSetAttribute(tcg<false, 0, false, 0>, cudaFuncAttributeMaxDynamicSharedMemorySize, SMEM_BYTES);
    cudaFuncSetAttribute(tcg<false, 0, false, 1>, cudaFuncAttributeMaxDynamicSharedMemorySize, SMEM_BYTES);
    cudaFuncSetAttribute(tcg<true, 2, true, 1>, cudaFuncAttributeMaxDynamicSharedMemorySize, SMEM_BYTES);
    cudaFuncSetAttribute(tcg<true, 0, true, 0>, cudaFuncAttributeMaxDynamicSharedMemorySize, SMEM_BYTES);

    const long long SNN = (long long)NN_ * NN_;   // sig branch stride
    const long long SZ4 = 4LL * NH_;              // part branch stride
    const long long SZO = 17825792LL;             // output z/rec branch stride
    const size_t lossoff = 53477376ul, predoff = 53477377ul;
    const size_t roff0 = 1048576ul;

    int neb = (ne + 255) / 256;

    // prologue
    round_copy_kernel<<<(NN_ * FIN_ + 255) / 256, 256>>>(X, Xr, NN_ * FIN_);
    round_copy_kernel<<<(FIN_ * HID_ + 255) / 256, 256>>>(Wsh, Wr, FIN_ * HID_);
    zero_int_kernel<<<16, 256>>>(cnt, NN_);
    hist_kernel<<<neb, 256>>>(arows, cnt, ne);
    exscan_kernel<<<1, 1024>>>(cnt, ptrR, nextR);
    tcg<false, 0, false, 0><<<64, 256, SMEM_BYTES>>>(Xr, Wr, bufA, 256, 512, 16, 2, 0, 0, 0, 0);
    scatter_kernel<<<neb, 256>>>(arows, acols, avals, nextR, colR, valR, ne);
    zero_int_kernel<<<16, 256>>>(cnt, NN_);
    hist_kernel<<<neb, 256>>>(acols, cnt, ne);
    exscan_kernel<<<1, 1024>>>(cnt, ptrC, nextC);
    scatter_kernel<<<neb, 256>>>(acols, arows, avals, nextC, colC, valC, ne);
    for (int b = 0; b < 3; b++) {
        round_copy_kernel<<<256, 256>>>(Wb[b], Wr + FIN_ * HID_ + b * 65536, HID_ * HID_);
        round_copy_kernel<<<256, 256>>>(Wg[b], Wr + FIN_ * HID_ + (3 + b) * 65536, HID_ * HID_);
    }
    // h = rtf32(relu(spmm(Xr @ Wsh)))
    spmm_csr_kernel<<<NN_, HID_>>>(ptrR, colR, valR, bufA, h, 2, 0, 0);

    // ---- all three branches batched via blockIdx.z ----
    const float* Wb0 = Wr + FIN_ * HID_;
    const float* Wg0 = Wr + FIN_ * HID_ + 3 * 65536;

    // z0 = rtf32(relu(spmm(h @ Wb)))
    tcg<false, 0, false, 0><<<dim3(64, 1, 3), 256, SMEM_BYTES>>>(
        h, Wb0, bufA, 256, 256, 8, 2, 0, 0, 65536, NH_);
    spmm_csr_kernel<<<dim3(NN_, 3), HID_>>>(ptrR, colR, valR, bufA, z0, 2, NH_, NH_);
    // sig = rtf32(sigmoid(z0 @ z0^T))  [symmetric]
    tcg<true, 2, true, 1><<<dim3(528, 1, 3), 256, SMEM_BYTES>>>(
        z0, z0, sig, 4096, 256, 8, 32, 0, NH_, NH_, SNN);
    // hW = rtf32(z0 @ Wg)
    tcg<false, 0, false, 1><<<dim3(64, 1, 3), 256, SMEM_BYTES>>>(
        z0, Wg0, bufA, 256, 256, 8, 2, 0, NH_, 65536, NH_);
    // t1 = A^T @ hW
    spmm_csr_kernel<<<dim3(NN_, 3), HID_>>>(ptrC, colC, valC, bufA, t1, 0, NH_, NH_);
    // t2 = rtf32(sig @ hW)  [split-K x4]
    tcg<false, 0, false, 0><<<dim3(64, 4, 3), 256, SMEM_BYTES>>>(
        sig, bufA, part, 256, 4096, 32, 2, NH_, SNN, NH_, SZ4);
    reduce4_round<<<dim3(1024, 3), 256>>>(part, t2, SZ4, NH_);
    // u1 = A @ t1
    spmm_csr_kernel<<<dim3(NN_, 3), HID_>>>(ptrR, colR, valR, t1, u1, 0, NH_, NH_);
    // z = relu(sig @ t2 + u1)  [split-K x4]
    tcg<false, 0, false, 0><<<dim3(64, 4, 3), 256, SMEM_BYTES>>>(
        sig, t2, part, 256, 4096, 32, 2, NH_, SNN, NH_, SZ4);
    reduce4_addrelu<<<dim3(1024, 3), 256>>>(part, u1, out, zr, SZ4, NH_, SZO, NH_);
    // rec = zr @ zr^T  [symmetric]
    tcg<true, 0, true, 0><<<dim3(528, 1, 3), 256, SMEM_BYTES>>>(
        zr, zr, out + roff0, 4096, 256, 8, 32, 0, NH_, NH_, SZO);

    pred_kernel<<<16, 256>>>(out, out + SZO, linW, linb, out + predoff);
    write_loss_kernel<<<1, 1>>>(out + lossoff);
}

// round 11
// speedup vs baseline: 1.6948x; 1.4202x over previous
#include <cuda_runtime.h>
#include <cuda_fp16.h>
#include <cstdint>

#define NN_ 4096
#define FIN_ 512
#define HID_ 256
#define NE_MAX 131072
#define NH_ (NN_ * HID_)

// ---------------- scratch ----------------
__device__ __align__(256) __half g_Xh[NN_ * FIN_];
__device__ __align__(256) __half g_WT[FIN_ * HID_ + 6 * HID_ * HID_];  // WshT, WbT[3], WgT[3]
__device__ __align__(256) __half g_h[NH_];
__device__ __align__(256) __half g_z0[3][NH_];
__device__ __align__(256) float  g_bufA[3][NH_];
__device__ __align__(256) __half g_sig[3][(size_t)NN_ * NN_];
__device__ __align__(256) __half g_hW[3][NH_];
__device__ __align__(256) __half g_hWT[3][NH_];
__device__ __align__(256) float  g_t1[3][NH_];
__device__ __align__(256) float  g_u1[3][NH_];
__device__ __align__(256) __half g_t2T[3][NH_];   // holds t2^T * 2^-8
__device__ __align__(256) __half g_zr[3][NH_];    // holds z * 2^-16
__device__ __align__(256) float  g_part[3][4 * NH_];

__device__ int   g_cnt[NN_];
__device__ int   g_ptrR[NN_ + 1];
__device__ int   g_nextR[NN_];
__device__ int   g_colR[NE_MAX];
__device__ float g_valR[NE_MAX];
__device__ int   g_ptrC[NN_ + 1];
__device__ int   g_nextC[NN_];
__device__ int   g_colC[NE_MAX];
__device__ float g_valC[NE_MAX];

// ---------------- helpers ----------------
__device__ __forceinline__ uint32_t smem_u32(const void* p) {
    uint32_t a;
    asm("{ .reg .u64 t; cvta.to.shared.u64 t, %1; cvt.u32.u64 %0, t; }" : "=r"(a) : "l"(p));
    return a;
}
#define CP16(d, s) asm volatile("cp.async.ca.shared.global [%0], [%1], 16;" :: "r"(d), "l"(s))
#define CPCOMMIT() asm volatile("cp.async.commit_group;" ::: "memory")
#define CPWAIT0() asm volatile("cp.async.wait_group 0;" ::: "memory")

// ---------------- fp16 mma.sync GEMM (8 warps, 64x32 warp tile, m16n8k16) ----------------
// C = epi(A[M,K] @ B[Nc,K]^T), A/B half K-major.
// EPI: 0 none, 1 sigmoid, 2 scale by 2^32 (rec from zr=z*2^-16).
// OM: 0 f32 C, 1 half C. SYM: symmetric mirror via smem-staged transpose.
// Batched: blockIdx.z = branch (aS/bS/cS element strides); blockIdx.y = split-K (C += y*cstride).
static constexpr int SMEM_BYTES = 128 * 129 * 4;  // 66048 >= pipeline 40960

template <int EPI, bool SYM, int OM>
__global__ __launch_bounds__(256) void tcg(
    const __half* __restrict__ A, const __half* __restrict__ B, void* __restrict__ Cv,
    int Nc, int K, int KCn, int tilesN, long long cstride,
    long long aS, long long bS, long long cS) {
    extern __shared__ float smf[];
    __half* smh = reinterpret_cast<__half*>(smf);
    const int tid = threadIdx.x, lane = tid & 31, wid = tid >> 5;
    const int wm = wid >> 2, wn = wid & 3;
    const int g = lane >> 2, t = lane & 3;

    A += (size_t)blockIdx.z * aS;
    B += (size_t)blockIdx.z * bS;
    const size_t coff = (size_t)blockIdx.z * cS + (size_t)blockIdx.y * cstride;
    float* Cf = (float*)Cv;
    __half* Ch = (__half*)Cv;

    int i, j;
    if (SYM) {
        int b = blockIdx.x, row = 0;
        while (b >= tilesN - row) { b -= tilesN - row; row++; }
        i = row; j = row + b;
    } else {
        i = blockIdx.x / tilesN; j = blockIdx.x % tilesN;
    }
    const int m0 = i * 128, n0 = j * 128;
    const int kb = blockIdx.y * KCn;
    const uint32_t sbase = smem_u32(smf);

    float acc[4][4][4];
    #pragma unroll
    for (int a = 0; a < 4; a++)
        #pragma unroll
        for (int b = 0; b < 4; b++)
            #pragma unroll
            for (int c = 0; c < 4; c++) acc[a][b][c] = 0.f;

    // smem (halves): A stages at 0 / 5120, B at 10240 / 15360; row stride 40 halves
    auto load_tile = [&](int akc, int buf) {
        int r = tid >> 1, c0 = (tid & 1) * 16;
        const __half* sA = A + (size_t)(m0 + r) * K + akc * 32 + c0;
        uint32_t dA = sbase + (uint32_t)(buf * 5120 + r * 40 + c0) * 2;
        CP16(dA, sA); CP16(dA + 16, sA + 8);
        const __half* sB = B + (size_t)(n0 + r) * K + akc * 32 + c0;
        uint32_t dB = sbase + (uint32_t)(10240 + buf * 5120 + r * 40 + c0) * 2;
        CP16(dB, sB); CP16(dB + 16, sB + 8);
    };

    load_tile(kb, 0);
    CPCOMMIT();
    int buf = 0;
    for (int c = 0; c < KCn; c++) {
        CPWAIT0();
        __syncthreads();
        if (c + 1 < KCn) { load_tile(kb + c + 1, buf ^ 1); CPCOMMIT(); }
        const uint32_t* As = (const uint32_t*)(smh + buf * 5120);        // 20 u32/row
        const uint32_t* Bs = (const uint32_t*)(smh + 10240 + buf * 5120);
        #pragma unroll
        for (int ks = 0; ks < 2; ks++) {
            uint32_t a[4][4], bb[4][2];
            #pragma unroll
            for (int mf = 0; mf < 4; mf++) {
                const uint32_t* ap = As + (wm * 64 + mf * 16 + g) * 20 + ks * 8 + t;
                a[mf][0] = ap[0]; a[mf][1] = ap[160]; a[mf][2] = ap[4]; a[mf][3] = ap[164];
            }
            #pragma unroll
            for (int nf = 0; nf < 4; nf++) {
                const uint32_t* bp = Bs + (wn * 32 + nf * 8 + g) * 20 + ks * 8 + t;
                bb[nf][0] = bp[0]; bb[nf][1] = bp[4];
            }
            #pragma unroll
            for (int nf = 0; nf < 4; nf++)
                #pragma unroll
                for (int mf = 0; mf < 4; mf++)
                    asm volatile(
                        "mma.sync.aligned.m16n8k16.row.col.f32.f16.f16.f32 "
                        "{%0,%1,%2,%3}, {%4,%5,%6,%7}, {%8,%9}, {%0,%1,%2,%3};"
                        : "+f"(acc[mf][nf][0]), "+f"(acc[mf][nf][1]),
                          "+f"(acc[mf][nf][2]), "+f"(acc[mf][nf][3])
                        : "r"(a[mf][0]), "r"(a[mf][1]), "r"(a[mf][2]), "r"(a[mf][3]),
                          "r"(bb[nf][0]), "r"(bb[nf][1]));
        }
        __syncthreads();
        buf ^= 1;
    }

    // epilogue
    #pragma unroll
    for (int mf = 0; mf < 4; mf++) {
        int lr = wm * 64 + mf * 16 + g;
        #pragma unroll
        for (int nf = 0; nf < 4; nf++) {
            int lc = wn * 32 + nf * 8 + 2 * t;
            float w[4];
            #pragma unroll
            for (int q = 0; q < 4; q++) {
                float x = acc[mf][nf][q];
                if (EPI == 1) x = 1.f / (1.f + __expf(-x));
                else if (EPI == 2) x *= 4294967296.f;  // 2^32: undo zr = z*2^-16 on both operands
                w[q] = x;
            }
            size_t i0 = coff + (size_t)(m0 + lr) * Nc + n0 + lc;
            size_t i1 = coff + (size_t)(m0 + lr + 8) * Nc + n0 + lc;
            if (OM == 0) {
                *reinterpret_cast<float2*>(Cf + i0) = make_float2(w[0], w[1]);
                *reinterpret_cast<float2*>(Cf + i1) = make_float2(w[2], w[3]);
            } else {
                *reinterpret_cast<__half2*>(Ch + i0) = __floats2half2_rn(w[0], w[1]);
                *reinterpret_cast<__half2*>(Ch + i1) = __floats2half2_rn(w[2], w[3]);
            }
            if (SYM) {
                if (OM == 0) {
                    smf[lr * 129 + lc] = w[0]; smf[lr * 129 + lc + 1] = w[1];
                    smf[(lr + 8) * 129 + lc] = w[2]; smf[(lr + 8) * 129 + lc + 1] = w[3];
                } else {
                    smh[lr * 129 + lc] = __float2half_rn(w[0]);
                    smh[lr * 129 + lc + 1] = __float2half_rn(w[1]);
                    smh[(lr + 8) * 129 + lc] = __float2half_rn(w[2]);
                    smh[(lr + 8) * 129 + lc + 1] = __float2half_rn(w[3]);
                }
            }
        }
    }
    if (SYM && i != j) {
        __syncthreads();
        int col = tid & 127;
        if (OM == 0) {
            #pragma unroll 4
            for (int c = tid >> 7; c < 128; c += 2)
                Cf[coff + (size_t)(n0 + c) * Nc + m0 + col] = smf[col * 129 + c];
        } else {
            #pragma unroll 4
            for (int c = tid >> 7; c < 128; c += 2)
                Ch[coff + (size_t)(n0 + c) * Nc + m0 + col] = smh[col * 129 + c];
        }
    }
}

// ---------------- split-K reduces ----------------
// t2T = half((sum of partials) * 2^-8)  — power-of-2 scale keeps fp16 in range, lossless mantissa
__global__ void reduce4_half(const float* __restrict__ p, __half* __restrict__ o,
                             long long pS, long long oS) {
    const float* pp = p + (size_t)blockIdx.y * pS;
    __half* oo = o + (size_t)blockIdx.y * oS;
    int i = (blockIdx.x * blockDim.x + threadIdx.x) * 4;
    float4 a = *reinterpret_cast<const float4*>(pp + i);
    float4 b = *reinterpret_cast<const float4*>(pp + NH_ + i);
    float4 c = *reinterpret_cast<const float4*>(pp + 2 * NH_ + i);
    float4 d = *reinterpret_cast<const float4*>(pp + 3 * NH_ + i);
    const float s = 0.00390625f;  // 2^-8
    __half2 h0 = __floats2half2_rn((a.x + b.x + c.x + d.x) * s, (a.y + b.y + c.y + d.y) * s);
    __half2 h1 = __floats2half2_rn((a.z + b.z + c.z + d.z) * s, (a.w + b.w + c.w + d.w) * s);
    *reinterpret_cast<__half2*>(oo + i) = h0;
    *reinterpret_cast<__half2*>(oo + i + 2) = h1;
}
// z = relu((sum of partials)*2^8 + u1)  (partials were sig @ (t2*2^-8));  zr = half(z * 2^-16)
__global__ void reduce4_addrelu(const float* __restrict__ p, const float* __restrict__ u,
                                float* __restrict__ z, __half* __restrict__ zr,
                                long long pS, long long uS, long long zS, long long zrS) {
    const float* pp = p + (size_t)blockIdx.y * pS;
    const float* uu4 = u + (size_t)blockIdx.y * uS;
    float* zz4 = z + (size_t)blockIdx.y * zS;
    __half* rr4 = zr + (size_t)blockIdx.y * zrS;
    int i = (blockIdx.x * blockDim.x + threadIdx.x) * 4;
    float4 a = *reinterpret_cast<const float4*>(pp + i);
    float4 b = *reinterpret_cast<const float4*>(pp + NH_ + i);
    float4 c = *reinterpret_cast<const float4*>(pp + 2 * NH_ + i);
    float4 d = *reinterpret_cast<const float4*>(pp + 3 * NH_ + i);
    float4 uu = *reinterpret_cast<const float4*>(uu4 + i);
    const float up = 256.f;  // 2^8: undo t2 storage scale
    float4 zz;
    zz.x = fmaxf((a.x + b.x + c.x + d.x) * up + uu.x, 0.f);
    zz.y = fmaxf((a.y + b.y + c.y + d.y) * up + uu.y, 0.f);
    zz.z = fmaxf((a.z + b.z + c.z + d.z) * up + uu.z, 0.f);
    zz.w = fmaxf((a.w + b.w + c.w + d.w) * up + uu.w, 0.f);
    *reinterpret_cast<float4*>(zz4 + i) = zz;
    const float s = 1.52587890625e-05f;  // 2^-16
    *reinterpret_cast<__half2*>(rr4 + i) = __floats2half2_rn(zz.x * s, zz.y * s);
    *reinterpret_cast<__half2*>(rr4 + i + 2) = __floats2half2_rn(zz.z * s, zz.w * s);
}

// ---------------- CSR build ----------------
__global__ void zero_int_kernel(int* p, int n) {
    int i = blockIdx.x * blockDim.x + threadIdx.x;
    if (i < n) p[i] = 0;
}
__global__ void hist_kernel(const int* __restrict__ k, int* __restrict__ c, int ne) {
    int i = blockIdx.x * blockDim.x + threadIdx.x;
    if (i < ne) atomicAdd(&c[k[i]], 1);
}
__global__ void exscan_kernel(const int* __restrict__ cnt, int* __restrict__ rp, int* __restrict__ nx) {
    __shared__ int sums[1024];
    int t = threadIdx.x;
    int v0 = cnt[t * 4], v1 = cnt[t * 4 + 1], v2 = cnt[t * 4 + 2], v3 = cnt[t * 4 + 3];
    sums[t] = v0 + v1 + v2 + v3;
    __syncthreads();
    for (int off = 1; off < 1024; off <<= 1) {
        int x = (t >= off) ? sums[t - off] : 0;
        __syncthreads();
        sums[t] += x;
        __syncthreads();
    }
    int run = (t > 0) ? sums[t - 1] : 0;
    rp[t * 4] = run; nx[t * 4] = run; run += v0;
    rp[t * 4 + 1] = run; nx[t * 4 + 1] = run; run += v1;
    rp[t * 4 + 2] = run; nx[t * 4 + 2] = run; run += v2;
    rp[t * 4 + 3] = run; nx[t * 4 + 3] = run; run += v3;
    if (t == 1023) rp[4096] = run;
}
__global__ void scatter_kernel(const int* __restrict__ k, const int* __restrict__ o,
                               const float* __restrict__ v, int* __restrict__ nx,
                               int* __restrict__ ec, float* __restrict__ ev, int ne) {
    int i = blockIdx.x * blockDim.x + threadIdx.x;
    if (i < ne) {
        int p = atomicAdd(&nx[k[i]], 1);
        ec[p] = o[i];
        ev[p] = v[i];
    }
}

// ---------------- SpMM (templated in/out dtype; batched over blockIdx.y) ----------------
template <typename TI, typename TO>
__global__ __launch_bounds__(HID_) void spmm_csr(
    const int* __restrict__ rowptr, const int* __restrict__ ecol,
    const float* __restrict__ eval, const TI* __restrict__ in,
    TO* __restrict__ out, int relu, long long inS, long long outS) {
    const TI* inp = in + (size_t)blockIdx.y * inS;
    TO* outp = out + (size_t)blockIdx.y * outS;
    int r = blockIdx.x, f = threadIdx.x;
    int s = rowptr[r], e = rowptr[r + 1];
    __shared__ int   scol[HID_];
    __shared__ float sval[HID_];
    float acc = 0.f;
    for (int base = s; base < e; base += HID_) {
        int n = e - base;
        if (n > HID_) n = HID_;
        if (f < n) { scol[f] = ecol[base + f]; sval[f] = eval[base + f]; }
        __syncthreads();
        #pragma unroll 4
        for (int i = 0; i < n; i++) acc += sval[i] * (float)inp[scol[i] * HID_ + f];
        __syncthreads();
    }
    if (relu) acc = fmaxf(acc, 0.f);
    outp[r * HID_ + f] = (TO)acc;
}

// ---------------- prep / head ----------------
__global__ void half_copy_kernel(const float* __restrict__ x, __half* __restrict__ y, int n) {
    int i = blockIdx.x * blockDim.x + threadIdx.x;
    if (i < n) y[i] = __float2half_rn(x[i]);
}
__global__ void transpose_half_kernel(const float* __restrict__ W, __half* __restrict__ WT,
                                      int K, int N) {
    int i = blockIdx.x * blockDim.x + threadIdx.x;
    if (i < K * N) {
        int k = i / N, n = i - k * N;
        WT[n * K + k] = __float2half_rn(W[i]);
    }
}
__global__ void pred_kernel(const float* __restrict__ z_iv, const float* __restrict__ z_c,
                            const float* __restrict__ linW, const float* __restrict__ linb,
                            float* __restrict__ out) {
    int i = blockIdx.x * blockDim.x + threadIdx.x;
    if (i >= NN_) return;
    float l0 = linb[0], l1 = linb[1];
    #pragma unroll 4
    for (int k = 0; k < HID_; k++) {
        float v = z_iv[i * HID_ + k];
        l0 += v * linW[k * 2];
        l1 += v * linW[k * 2 + 1];
    }
    #pragma unroll 4
    for (int k = 0; k < HID_; k++) {
        float v = z_c[i * HID_ + k];
        l0 += v * linW[(HID_ + k) * 2];
        l1 += v * linW[(HID_ + k) * 2 + 1];
    }
    float m = fmaxf(l0, l1);
    float lse = m + logf(expf(l0 - m) + expf(l1 - m));
    out[i * 2] = l0 - lse;
    out[i * 2 + 1] = l1 - lse;
}
__global__ void write_loss_kernel(float* p) { *p = 0.f; }

// ---------------- host ----------------
static void* sym(const void* s) { void* p = nullptr; cudaGetSymbolAddress(&p, s); return p; }

extern "C" void kernel_launch(void* const* d_in, const int* in_sizes, int n_in,
                              void* d_out, int out_size) {
    const float* X     = (const float*)d_in[0];
    const int*   arows = (const int*)d_in[1];
    const int*   acols = (const int*)d_in[2];
    const float* avals = (const float*)d_in[3];
    const float* Wsh   = (const float*)d_in[4];
    const float* Wb[3] = {(const float*)d_in[5], (const float*)d_in[6], (const float*)d_in[7]};
    const float* Wg[3] = {(const float*)d_in[8], (const float*)d_in[9], (const float*)d_in[10]};
    const float* linW  = (const float*)d_in[11];
    const float* linb  = (const float*)d_in[12];
    float* out = (float*)d_out;
    int ne = in_sizes[1];

    __half* Xh  = (__half*)sym(g_Xh);
    __half* WT  = (__half*)sym(g_WT);
    __half* h   = (__half*)sym(g_h);
    __half* z0  = (__half*)sym(g_z0);
    float*  bufA = (float*)sym(g_bufA);
    __half* sig = (__half*)sym(g_sig);
    __half* hW  = (__half*)sym(g_hW);
    __half* hWT = (__half*)sym(g_hWT);
    float*  t1  = (float*)sym(g_t1);
    float*  u1  = (float*)sym(g_u1);
    __half* t2T = (__half*)sym(g_t2T);
    __half* zr  = (__half*)sym(g_zr);
    float*  part = (float*)sym(g_part);
    int* cnt = (int*)sym(g_cnt);
    int* ptrR = (int*)sym(g_ptrR); int* nextR = (int*)sym(g_nextR);
    int* colR = (int*)sym(g_colR); float* valR = (float*)sym(g_valR);
    int* ptrC = (int*)sym(g_ptrC); int* nextC = (int*)sym(g_nextC);
    int* colC = (int*)sym(g_colC); float* valC = (float*)sym(g_valC);

    cudaFuncSetAttribute(tcg<0, false, 0>, cudaFuncAttributeMaxDynamicSharedMemorySize, SMEM_BYTES);
    cudaFuncSetAttribute(tcg<0, false, 1>, cudaFuncAttributeMaxDynamicSharedMemorySize, SMEM_BYTES);
    cudaFuncSetAttribute(tcg<1, true, 1>, cudaFuncAttributeMaxDynamicSharedMemorySize, SMEM_BYTES);
    cudaFuncSetAttribute(tcg<2, true, 0>, cudaFuncAttributeMaxDynamicSharedMemorySize, SMEM_BYTES);

    const long long SNN = (long long)NN_ * NN_;
    const long long SZ4 = 4LL * NH_;
    const long long SZO = 17825792LL;
    const size_t lossoff = 53477376ul, predoff = 53477377ul;
    const size_t roff0 = 1048576ul;
    __half* WbT0 = WT + FIN_ * HID_;
    __half* WgT0 = WT + FIN_ * HID_ + 3 * 65536;

    int neb = (ne + 255) / 256;

    // prologue (launch #6 = G1 GEMM for ncu -s 5 -c 1)
    half_copy_kernel<<<(NN_ * FIN_ + 255) / 256, 256>>>(X, Xh, NN_ * FIN_);
    transpose_half_kernel<<<(FIN_ * HID_ + 255) / 256, 256>>>(Wsh, WT, FIN_, HID_);
    zero_int_kernel<<<16, 256>>>(cnt, NN_);
    hist_kernel<<<neb, 256>>>(arows, cnt, ne);
    exscan_kernel<<<1, 1024>>>(cnt, ptrR, nextR);
    // G1: bufA = Xh @ WshT^T  (f32)
    tcg<0, false, 0><<<64, 256, SMEM_BYTES>>>(Xh, WT, bufA, 256, 512, 16, 2, 0, 0, 0, 0);
    scatter_kernel<<<neb, 256>>>(arows, acols, avals, nextR, colR, valR, ne);
    zero_int_kernel<<<16, 256>>>(cnt, NN_);
    hist_kernel<<<neb, 256>>>(acols, cnt, ne);
    exscan_kernel<<<1, 1024>>>(cnt, ptrC, nextC);
    scatter_kernel<<<neb, 256>>>(acols, arows, avals, nextC, colC, valC, ne);
    for (int b = 0; b < 3; b++) {
        transpose_half_kernel<<<256, 256>>>(Wb[b], WbT0 + b * 65536, HID_, HID_);
        transpose_half_kernel<<<256, 256>>>(Wg[b], WgT0 + b * 65536, HID_, HID_);
    }
    // h = half(relu(spmm(bufA)))
    spmm_csr<float, __half><<<NN_, HID_>>>(ptrR, colR, valR, bufA, h, 1, 0, 0);

    // ---- three branches batched via blockIdx.z ----
    // z0 = half(relu(spmm(h @ WbT^T)))
    tcg<0, false, 0><<<dim3(64, 1, 3), 256, SMEM_BYTES>>>(
        h, WbT0, bufA, 256, 256, 8, 2, 0, 0, 65536, NH_);
    spmm_csr<float, __half><<<dim3(NN_, 3), HID_>>>(ptrR, colR, valR, bufA, z0, 1, NH_, NH_);
    // sig = half(sigmoid(z0 @ z0^T))  [symmetric, mirror]
    tcg<1, true, 1><<<dim3(528, 1, 3), 256, SMEM_BYTES>>>(
        z0, z0, sig, 4096, 256, 8, 32, 0, NH_, NH_, SNN);
    // hW = half(z0 @ WgT^T)  [for spmm]
    tcg<0, false, 1><<<dim3(64, 1, 3), 256, SMEM_BYTES>>>(
        z0, WgT0, hW, 256, 256, 8, 2, 0, NH_, 65536, NH_);
    // hWT = half(WgT @ z0^T) = hW^T  [K-major B for t2T GEMM]
    tcg<0, false, 1><<<dim3(64, 1, 3), 256, SMEM_BYTES>>>(
        WgT0, z0, hWT, 4096, 256, 8, 32, 0, 65536, NH_, NH_);
    // t1 = A^T @ hW  (f32)
    spmm_csr<__half, float><<<dim3(NN_, 3), HID_>>>(ptrC, colC, valC, hW, t1, 0, NH_, NH_);
    // t2T = half((hWT @ sig) * 2^-8)  [split-K x4; = (sig@hW)^T * 2^-8 by symmetry]
    tcg<0, false, 0><<<dim3(64, 4, 3), 256, SMEM_BYTES>>>(
        hWT, sig, part, 4096, 4096, 32, 32, NH_, NH_, SNN, SZ4);
    reduce4_half<<<dim3(1024, 3), 256>>>(part, t2T, SZ4, NH_);
    // u1 = A @ t1  (f32)
    spmm_csr<float, float><<<dim3(NN_, 3), HID_>>>(ptrR, colR, valR, t1, u1, 0, NH_, NH_);
    // z = relu((sig @ t2T^T)*2^8 + u1)  [split-K x4] -> out f32, zr = z*2^-16 half
    tcg<0, false, 0><<<dim3(64, 4, 3), 256, SMEM_BYTES>>>(
        sig, t2T, part, 256, 4096, 32, 2, NH_, SNN, NH_, SZ4);
    reduce4_addrelu<<<dim3(1024, 3), 256>>>(part, u1, out, zr, SZ4, NH_, SZO, NH_);
    // rec = (zr @ zr^T) * 2^32  [symmetric, f32 out]
    tcg<2, true, 0><<<dim3(528, 1, 3), 256, SMEM_BYTES>>>(
        zr, zr, out + roff0, 4096, 256, 8, 32, 0, NH_, NH_, SZO);

    pred_kernel<<<16, 256>>>(out, out + SZO, linW, linb, out + predoff);
    write_loss_kernel<<<1, 1>>>(out + lossoff);
}